// round 8
// baseline (speedup 1.0000x reference)
#include <cuda_runtime.h>
#include <math.h>
#include <cstdint>

#define Bn 8
#define Sn 2048
#define En 1024
#define Hn 64
#define NSPLIT 4

// Scratch: q,k,v [B,S,H]; 4-way split-KV partials
__device__ float g_q[Bn * Sn * Hn];
__device__ float g_k[Bn * Sn * Hn];
__device__ float g_v[Bn * Sn * Hn];
__device__ float g_op[NSPLIT * Bn * Sn * Hn];
__device__ float g_ml[NSPLIT * Bn * Sn * 2];

// m16n8k16 bf16 mma: D += A*B, fp32 accumulate. regs hold bf16x2 pairs.
__device__ __forceinline__ void mma_bf16(float d[4], const uint32_t a[4],
                                         uint32_t b0, uint32_t b1)
{
    asm volatile(
        "mma.sync.aligned.m16n8k16.row.col.f32.bf16.bf16.f32 "
        "{%0,%1,%2,%3}, {%4,%5,%6,%7}, {%8,%9}, {%0,%1,%2,%3};"
        : "+f"(d[0]), "+f"(d[1]), "+f"(d[2]), "+f"(d[3])
        : "r"(a[0]), "r"(a[1]), "r"(a[2]), "r"(a[3]), "r"(b0), "r"(b1));
}

// Split a float pair into bf16x2 hi + bf16x2 residual. lo half = x0 (lower k).
__device__ __forceinline__ void split2(float x0, float x1,
                                       uint32_t& h, uint32_t& l)
{
    uint32_t hp;
    asm("cvt.rn.bf16x2.f32 %0, %1, %2;" : "=r"(hp) : "f"(x1), "f"(x0));
    float h0 = __uint_as_float(hp << 16);
    float h1 = __uint_as_float(hp & 0xffff0000u);
    uint32_t lp;
    asm("cvt.rn.bf16x2.f32 %0, %1, %2;" : "=r"(lp) : "f"(x1 - h1), "f"(x0 - h0));
    h = hp;
    l = lp;
}

__device__ __forceinline__ void mma3(float d[4],
                                     const uint32_t ah[4], const uint32_t al[4],
                                     uint32_t bh0, uint32_t bl0,
                                     uint32_t bh1, uint32_t bl1)
{
    mma_bf16(d, ah, bh0, bh1);
    mma_bf16(d, ah, bl0, bl1);
    mma_bf16(d, al, bh0, bh1);
}

// ---------------------------------------------------------------------------
// Projection: [16384,1024] x [1024,192] (+bias) -> g_q|g_k|g_v
// grid (256, 2): CTA = 64 rows x 96 cols (nh = col half). 8 warps:
// wm = warp&3 (16-row group), wn = warp>>2 (48-col group).
// Software-pipelined: register prefetch + double-buffered smem chunks (k=32).
// ---------------------------------------------------------------------------
#define SXP 20
#define SWP 20
#define PJ_XH(b) ((b) * 64 * SXP)
#define PJ_XL(b) (2 * 64 * SXP + (b) * 64 * SXP)
#define PJ_WH(b) (4 * 64 * SXP + (b) * 96 * SWP)
#define PJ_WL(b) (4 * 64 * SXP + 2 * 96 * SWP + (b) * 96 * SWP)
#define PJ_B     (4 * 64 * SXP + 4 * 96 * SWP)
#define PJ_TOT   (PJ_B + 96)

__global__ __launch_bounds__(256) void proj_mma_kernel(
    const float* __restrict__ x,
    const float* __restrict__ Wq, const float* __restrict__ bq,
    const float* __restrict__ Wk, const float* __restrict__ bk,
    const float* __restrict__ Wv, const float* __restrict__ bv)
{
    extern __shared__ uint32_t smu[];
    float* sB = (float*)(smu + PJ_B);

    const int tid  = threadIdx.x;
    const int warp = tid >> 5;
    const int lane = tid & 31;
    const int g    = lane >> 2;
    const int tg   = lane & 3;
    const int wm   = warp & 3;
    const int wn   = warp >> 2;
    const int row0 = blockIdx.x * 64;
    const int nh   = blockIdx.y;          // 0 or 1: 96-col half

    if (tid < 96) {
        int col = nh * 96 + tid;
        const float* bb = (col < 64) ? bq : (col < 128 ? bk : bv);
        sB[tid] = bb[col & 63];
    }

    // loader indices (fixed per thread)
    const int xr0 = tid >> 3;            // 0..31 (u=0), +32 (u=1)
    const int xc  = tid & 7;
    // W loader: u in {0,1}, idx = tid + 256u, valid if idx < 384
    //   nc = idx>>4 (0..23) -> local col 4*nc; r = idx&15 (pair index)

    float acc[6][4];
    #pragma unroll
    for (int t = 0; t < 6; t++)
        #pragma unroll
        for (int i = 0; i < 4; i++) acc[t][i] = 0.0f;

    float4 xreg[2];
    float4 wa[2], wb[2];

    auto ldg_chunk = [&](int c) {
        const int k0 = c * 32;
        #pragma unroll
        for (int u = 0; u < 2; u++) {
            int r = xr0 + 32 * u;
            xreg[u] = *reinterpret_cast<const float4*>(
                &x[(size_t)(row0 + r) * En + k0 + 4 * xc]);
        }
        #pragma unroll
        for (int u = 0; u < 2; u++) {
            int idx = tid + 256 * u;
            if (idx < 384) {
                int nc = idx >> 4, r = idx & 15;
                int col = nh * 96 + 4 * nc;
                const float* Wm = (col < 64) ? Wq : (col < 128 ? Wk : Wv);
                const int lcol = col & 63;
                wa[u] = *reinterpret_cast<const float4*>(
                    &Wm[(size_t)(k0 + 2 * r) * Hn + lcol]);
                wb[u] = *reinterpret_cast<const float4*>(
                    &Wm[(size_t)(k0 + 2 * r + 1) * Hn + lcol]);
            }
        }
    };

    auto sts_chunk = [&](int buf) {
        uint32_t* sXh = smu + PJ_XH(buf);
        uint32_t* sXl = smu + PJ_XL(buf);
        uint32_t* sWh = smu + PJ_WH(buf);
        uint32_t* sWl = smu + PJ_WL(buf);
        #pragma unroll
        for (int u = 0; u < 2; u++) {
            int r = xr0 + 32 * u;
            uint32_t h0, l0, h1, l1;
            split2(xreg[u].x, xreg[u].y, h0, l0);
            split2(xreg[u].z, xreg[u].w, h1, l1);
            uint2 hh; hh.x = h0; hh.y = h1;
            uint2 ll; ll.x = l0; ll.y = l1;
            *reinterpret_cast<uint2*>(&sXh[r * SXP + 2 * xc]) = hh;
            *reinterpret_cast<uint2*>(&sXl[r * SXP + 2 * xc]) = ll;
        }
        #pragma unroll
        for (int u = 0; u < 2; u++) {
            int idx = tid + 256 * u;
            if (idx < 384) {
                int nc = idx >> 4, r = idx & 15;
                const float* fa = (const float*)&wa[u];
                const float* fb = (const float*)&wb[u];
                #pragma unroll
                for (int j = 0; j < 4; j++) {
                    uint32_t h, l;
                    split2(fa[j], fb[j], h, l);
                    sWh[(4 * nc + j) * SWP + r] = h;
                    sWl[(4 * nc + j) * SWP + r] = l;
                }
            }
        }
    };

    ldg_chunk(0);
    sts_chunk(0);
    __syncthreads();

    const int NCH = En / 32;
    for (int c = 0; c < NCH; c++) {
        const int buf = c & 1;
        if (c + 1 < NCH) ldg_chunk(c + 1);

        uint32_t* sXh = smu + PJ_XH(buf);
        uint32_t* sXl = smu + PJ_XL(buf);
        uint32_t* sWh = smu + PJ_WH(buf);
        uint32_t* sWl = smu + PJ_WL(buf);

        #pragma unroll
        for (int kk = 0; kk < 2; kk++) {
            uint32_t ah[4], al[4];
            const int ar0 = (16 * wm + g) * SXP + 8 * kk + tg;
            ah[0] = sXh[ar0];               al[0] = sXl[ar0];
            ah[1] = sXh[ar0 + 8 * SXP];     al[1] = sXl[ar0 + 8 * SXP];
            ah[2] = sXh[ar0 + 4];           al[2] = sXl[ar0 + 4];
            ah[3] = sXh[ar0 + 8 * SXP + 4]; al[3] = sXl[ar0 + 8 * SXP + 4];
            #pragma unroll
            for (int t = 0; t < 6; t++) {
                const int nl = wn * 48 + 8 * t + g;
                const int b0 = nl * SWP + 8 * kk + tg;
                mma3(acc[t], ah, al,
                     sWh[b0], sWl[b0], sWh[b0 + 4], sWl[b0 + 4]);
            }
        }

        if (c + 1 < NCH) sts_chunk((c + 1) & 1);
        __syncthreads();
    }

    const int r0 = row0 + 16 * wm + g;
    #pragma unroll
    for (int t = 0; t < 6; t++) {
        const int lcl = wn * 48 + 8 * t + 2 * tg;   // local col in this half
        const int col = nh * 96 + lcl;
        float* dst = (col < 64) ? g_q : (col < 128 ? g_k : g_v);
        const int lcol = col & 63;
        float2 v0, v1;
        v0.x = acc[t][0] + sB[lcl];
        v0.y = acc[t][1] + sB[lcl + 1];
        v1.x = acc[t][2] + sB[lcl];
        v1.y = acc[t][3] + sB[lcl + 1];
        *reinterpret_cast<float2*>(&dst[(size_t)r0 * Hn + lcol]) = v0;
        *reinterpret_cast<float2*>(&dst[(size_t)(r0 + 8) * Hn + lcol]) = v1;
    }
}

// ---------------------------------------------------------------------------
// Flash attention, 4-way split-KV, 3xBF16, P overlaid on K smem.
// CTA 64 q-rows, 4 warps. grid (32, 8, 4), heavy q-tiles first.
// ---------------------------------------------------------------------------
#define SKP 36
#define AT_KH 0                       // K hi -> later P hi (overlay)
#define AT_KL (AT_KH + 64 * SKP)      // K lo -> later P lo
#define AT_VH (AT_KL + 64 * SKP)
#define AT_VL (AT_VH + 64 * SKP)
#define AT_M  (AT_VL + 64 * SKP)
#define AT_TOT (AT_M + 64)

__global__ __launch_bounds__(128) void attn_mma_kernel(
    const int* __restrict__ mask)
{
    extern __shared__ uint32_t smu[];
    uint32_t* sKh = smu + AT_KH;   // doubles as sPh after S-MMA
    uint32_t* sKl = smu + AT_KL;   // doubles as sPl
    uint32_t* sVh = smu + AT_VH;
    uint32_t* sVl = smu + AT_VL;
    float*    sM  = (float*)(smu + AT_M);

    const int b    = blockIdx.y;
    const int qt   = (gridDim.x - 1) - blockIdx.x;
    const int z    = blockIdx.z;
    const int qbase = qt * 64;
    const int tid  = threadIdx.x;
    const int warp = tid >> 5;
    const int lane = tid & 31;
    const int g    = lane >> 2;
    const int tg   = lane & 3;
    const int wrow = warp * 16;

    const int nt  = qt + 1;
    const int jt_begin = (nt * z) / NSPLIT;
    const int jt_end   = (nt * (z + 1)) / NSPLIT;

    const float* qp = g_q + ((size_t)b * Sn + qbase + wrow) * Hn;
    const float* kp = g_k + (size_t)b * Sn * Hn;
    const float* vp = g_v + (size_t)b * Sn * Hn;

    // Q fragments (pre-scaled by 0.125), persistent hi/lo pair splits
    uint32_t qh[4][4], ql[4][4];
    #pragma unroll
    for (int kc = 0; kc < 4; kc++) {
        const int kb = 16 * kc + 2 * tg;
        float2 q0 = *reinterpret_cast<const float2*>(&qp[(size_t)g * Hn + kb]);
        float2 q1 = *reinterpret_cast<const float2*>(&qp[(size_t)(g + 8) * Hn + kb]);
        float2 q2 = *reinterpret_cast<const float2*>(&qp[(size_t)g * Hn + kb + 8]);
        float2 q3 = *reinterpret_cast<const float2*>(&qp[(size_t)(g + 8) * Hn + kb + 8]);
        split2(q0.x * 0.125f, q0.y * 0.125f, qh[kc][0], ql[kc][0]);
        split2(q1.x * 0.125f, q1.y * 0.125f, qh[kc][1], ql[kc][1]);
        split2(q2.x * 0.125f, q2.y * 0.125f, qh[kc][2], ql[kc][2]);
        split2(q3.x * 0.125f, q3.y * 0.125f, qh[kc][3], ql[kc][3]);
    }

    float m0 = -1e30f, m1 = -1e30f, l0 = 0.0f, l1 = 0.0f;
    float o[8][4];
    #pragma unroll
    for (int t = 0; t < 8; t++)
        #pragma unroll
        for (int i = 0; i < 4; i++) o[t][i] = 0.0f;

    for (int jt = jt_begin; jt < jt_end; jt++) {
        const int kbase = jt * 64;

        // K tile: pairs along h (contiguous within row)
        #pragma unroll
        for (int u = 0; u < 8; u++) {
            int idx = tid + 128 * u;
            int r = idx >> 4, c = idx & 15;
            float4 kv = *reinterpret_cast<const float4*>(
                &kp[(size_t)(kbase + r) * Hn + 4 * c]);
            uint32_t h0, l0_, h1, l1_;
            split2(kv.x, kv.y, h0, l0_);
            split2(kv.z, kv.w, h1, l1_);
            uint2 hh; hh.x = h0; hh.y = h1;
            uint2 ll; ll.x = l0_; ll.y = l1_;
            *reinterpret_cast<uint2*>(&sKh[r * SKP + 2 * c]) = hh;
            *reinterpret_cast<uint2*>(&sKl[r * SKP + 2 * c]) = ll;
        }
        // V tile: transposed pair-pack (pairs along kv)
        #pragma unroll
        for (int u = 0; u < 4; u++) {
            int idx = tid + 128 * u;
            int kvp = idx & 31;
            int c   = idx >> 5;
            float4 va = *reinterpret_cast<const float4*>(
                &vp[(size_t)(kbase + 2 * kvp) * Hn + 4 * c]);
            float4 vb = *reinterpret_cast<const float4*>(
                &vp[(size_t)(kbase + 2 * kvp + 1) * Hn + 4 * c]);
            const float* fa = (const float*)&va;
            const float* fb = (const float*)&vb;
            #pragma unroll
            for (int j = 0; j < 4; j++) {
                uint32_t h, l;
                split2(fa[j], fb[j], h, l);
                sVh[(4 * c + j) * SKP + kvp] = h;
                sVl[(4 * c + j) * SKP + kvp] = l;
            }
        }
        if (tid < 64)
            sM[tid] = (mask[b * Sn + kbase + tid] != 0) ? 0.0f : -1e30f;
        __syncthreads();

        // S = Q * K^T
        float s[8][4];
        #pragma unroll
        for (int t = 0; t < 8; t++)
            #pragma unroll
            for (int i = 0; i < 4; i++) s[t][i] = 0.0f;

        #pragma unroll
        for (int t = 0; t < 8; t++) {
            const int krow = (8 * t + g) * SKP;
            #pragma unroll
            for (int kc = 0; kc < 4; kc++) {
                const int i0 = krow + 8 * kc + tg;
                mma3(s[t], qh[kc], ql[kc],
                     sKh[i0], sKl[i0], sKh[i0 + 4], sKl[i0 + 4]);
            }
        }

        // Mask + row max
        const bool diag = (jt == qt);
        const int lrow0 = wrow + g;
        float rmax0 = -1e30f, rmax1 = -1e30f;
        #pragma unroll
        for (int t = 0; t < 8; t++) {
            const int c = 8 * t + 2 * tg;
            const float pa0 = sM[c], pa1 = sM[c + 1];
            s[t][0] += pa0; s[t][1] += pa1;
            s[t][2] += pa0; s[t][3] += pa1;
            if (diag) {
                if (c > lrow0)         s[t][0] = -1e30f;
                if (c + 1 > lrow0)     s[t][1] = -1e30f;
                if (c > lrow0 + 8)     s[t][2] = -1e30f;
                if (c + 1 > lrow0 + 8) s[t][3] = -1e30f;
            }
            rmax0 = fmaxf(rmax0, fmaxf(s[t][0], s[t][1]));
            rmax1 = fmaxf(rmax1, fmaxf(s[t][2], s[t][3]));
        }
        rmax0 = fmaxf(rmax0, __shfl_xor_sync(0xffffffffu, rmax0, 1));
        rmax0 = fmaxf(rmax0, __shfl_xor_sync(0xffffffffu, rmax0, 2));
        rmax1 = fmaxf(rmax1, __shfl_xor_sync(0xffffffffu, rmax1, 1));
        rmax1 = fmaxf(rmax1, __shfl_xor_sync(0xffffffffu, rmax1, 2));

        const float mn0 = fmaxf(m0, rmax0);
        const float mn1 = fmaxf(m1, rmax1);
        const float al0 = __expf(m0 - mn0);
        const float al1 = __expf(m1 - mn1);

        // exps into registers first; all warps must finish reading sK
        float p[8][4];
        float ps0 = 0.0f, ps1 = 0.0f;
        #pragma unroll
        for (int t = 0; t < 8; t++) {
            p[t][0] = __expf(s[t][0] - mn0);
            p[t][1] = __expf(s[t][1] - mn0);
            p[t][2] = __expf(s[t][2] - mn1);
            p[t][3] = __expf(s[t][3] - mn1);
            ps0 += p[t][0] + p[t][1];
            ps1 += p[t][2] + p[t][3];
        }
        __syncthreads();   // sK dead everywhere -> safe to overlay P

        #pragma unroll
        for (int t = 0; t < 8; t++) {
            uint32_t h, l;
            split2(p[t][0], p[t][1], h, l);
            sKh[(wrow + g) * SKP + 4 * t + tg] = h;    // sP overlay
            sKl[(wrow + g) * SKP + 4 * t + tg] = l;
            split2(p[t][2], p[t][3], h, l);
            sKh[(wrow + g + 8) * SKP + 4 * t + tg] = h;
            sKl[(wrow + g + 8) * SKP + 4 * t + tg] = l;
        }
        ps0 += __shfl_xor_sync(0xffffffffu, ps0, 1);
        ps0 += __shfl_xor_sync(0xffffffffu, ps0, 2);
        ps1 += __shfl_xor_sync(0xffffffffu, ps1, 1);
        ps1 += __shfl_xor_sync(0xffffffffu, ps1, 2);

        l0 = l0 * al0 + ps0;
        l1 = l1 * al1 + ps1;
        m0 = mn0;
        m1 = mn1;
        #pragma unroll
        for (int t = 0; t < 8; t++) {
            o[t][0] *= al0; o[t][1] *= al0;
            o[t][2] *= al1; o[t][3] *= al1;
        }
        __syncwarp();      // own P rows visible (only own warp reads them)

        // O += P * V
        #pragma unroll
        for (int kc = 0; kc < 4; kc++) {
            uint32_t ah[4], al_[4];
            const int pr = (wrow + g) * SKP + 8 * kc + tg;
            ah[0] = sKh[pr];               al_[0] = sKl[pr];
            ah[1] = sKh[pr + 8 * SKP];     al_[1] = sKl[pr + 8 * SKP];
            ah[2] = sKh[pr + 4];           al_[2] = sKl[pr + 4];
            ah[3] = sKh[pr + 8 * SKP + 4]; al_[3] = sKl[pr + 8 * SKP + 4];
            #pragma unroll
            for (int t = 0; t < 8; t++) {
                const int i0 = (8 * t + g) * SKP + 8 * kc + tg;
                mma3(o[t], ah, al_,
                     sVh[i0], sVl[i0], sVh[i0 + 4], sVl[i0 + 4]);
            }
        }
        __syncthreads();   // done with sP/sV before next tile overwrites
    }

    // Write unnormalized partials + m/l for this split
    float* op = g_op + (size_t)z * Bn * Sn * Hn;
    float* ml = g_ml + (size_t)z * Bn * Sn * 2;
    const size_t row0 = (size_t)b * Sn + qbase + wrow + g;
    #pragma unroll
    for (int t = 0; t < 8; t++) {
        const int col = 8 * t + 2 * tg;
        float2 w0, w1;
        w0.x = o[t][0]; w0.y = o[t][1];
        w1.x = o[t][2]; w1.y = o[t][3];
        *reinterpret_cast<float2*>(&op[row0 * Hn + col]) = w0;
        *reinterpret_cast<float2*>(&op[(row0 + 8) * Hn + col]) = w1;
    }
    if (tg == 0) {
        ml[row0 * 2]           = m0;
        ml[row0 * 2 + 1]       = l0;
        ml[(row0 + 8) * 2]     = m1;
        ml[(row0 + 8) * 2 + 1] = l1;
    }
}

// ---------------------------------------------------------------------------
// Merge the 4 KV splits: out = sum_z w_z * O_z / sum_z w_z * l_z
// ---------------------------------------------------------------------------
__global__ __launch_bounds__(256) void merge_kernel(float* __restrict__ out)
{
    const int tid = threadIdx.x;
    const int row = blockIdx.x * 16 + (tid >> 4);
    const int c4  = (tid & 15) * 4;

    float mz[NSPLIT], lz[NSPLIT];
    float m = -1e30f;
    #pragma unroll
    for (int zz = 0; zz < NSPLIT; zz++) {
        mz[zz] = g_ml[(size_t)zz * Bn * Sn * 2 + row * 2];
        lz[zz] = g_ml[(size_t)zz * Bn * Sn * 2 + row * 2 + 1];
        m = fmaxf(m, mz[zz]);
    }
    float denom = 0.0f;
    float w[NSPLIT];
    #pragma unroll
    for (int zz = 0; zz < NSPLIT; zz++) {
        w[zz] = __expf(mz[zz] - m);
        denom += w[zz] * lz[zz];
    }
    const float inv = 1.0f / denom;

    float4 r;
    r.x = 0.0f; r.y = 0.0f; r.z = 0.0f; r.w = 0.0f;
    #pragma unroll
    for (int zz = 0; zz < NSPLIT; zz++) {
        float4 a = *reinterpret_cast<const float4*>(
            &g_op[(size_t)zz * Bn * Sn * Hn + (size_t)row * Hn + c4]);
        r.x += w[zz] * a.x;
        r.y += w[zz] * a.y;
        r.z += w[zz] * a.z;
        r.w += w[zz] * a.w;
    }
    r.x *= inv; r.y *= inv; r.z *= inv; r.w *= inv;
    *reinterpret_cast<float4*>(&out[(size_t)row * Hn + c4]) = r;
}

extern "C" void kernel_launch(void* const* d_in, const int* in_sizes, int n_in,
                              void* d_out, int out_size)
{
    const float* x    = (const float*)d_in[0];
    const int*   mask = (const int*)d_in[1];
    const float* Wq   = (const float*)d_in[2];
    const float* bq   = (const float*)d_in[3];
    const float* Wk   = (const float*)d_in[4];
    const float* bk   = (const float*)d_in[5];
    const float* Wv   = (const float*)d_in[6];
    const float* bv   = (const float*)d_in[7];
    float* out = (float*)d_out;

    cudaFuncSetAttribute(proj_mma_kernel,
                         cudaFuncAttributeMaxDynamicSharedMemorySize,
                         PJ_TOT * (int)sizeof(uint32_t));
    cudaFuncSetAttribute(attn_mma_kernel,
                         cudaFuncAttributeMaxDynamicSharedMemorySize,
                         AT_TOT * (int)sizeof(uint32_t));

    dim3 gproj(Bn * Sn / 64, 2);
    proj_mma_kernel<<<gproj, 256, PJ_TOT * sizeof(uint32_t)>>>(
        x, Wq, bq, Wk, bk, Wv, bv);

    dim3 gattn(Sn / 64, Bn, NSPLIT);
    attn_mma_kernel<<<gattn, 128, AT_TOT * sizeof(uint32_t)>>>(mask);

    merge_kernel<<<Bn * Sn / 16, 256>>>(out);
}

// round 9
// speedup vs baseline: 1.2832x; 1.2832x over previous
#include <cuda_runtime.h>
#include <math.h>
#include <cstdint>

#define Bn 8
#define Sn 2048
#define En 1024
#define Hn 64
#define NSPLIT 4

// Scratch: q,k,v [B,S,H]; 4-way split-KV partials; pre-split W
__device__ float g_q[Bn * Sn * Hn];
__device__ float g_k[Bn * Sn * Hn];
__device__ float g_v[Bn * Sn * Hn];
__device__ float g_op[NSPLIT * Bn * Sn * Hn];
__device__ float g_ml[NSPLIT * Bn * Sn * 2];
// W pre-split: [192 n][512 kp x (h,l)] interleaved u32 = 768 KB
__device__ uint32_t g_wi[192 * 1024];

// m16n8k16 bf16 mma: D += A*B, fp32 accumulate. regs hold bf16x2 pairs.
__device__ __forceinline__ void mma_bf16(float d[4], const uint32_t a[4],
                                         uint32_t b0, uint32_t b1)
{
    asm volatile(
        "mma.sync.aligned.m16n8k16.row.col.f32.bf16.bf16.f32 "
        "{%0,%1,%2,%3}, {%4,%5,%6,%7}, {%8,%9}, {%0,%1,%2,%3};"
        : "+f"(d[0]), "+f"(d[1]), "+f"(d[2]), "+f"(d[3])
        : "r"(a[0]), "r"(a[1]), "r"(a[2]), "r"(a[3]), "r"(b0), "r"(b1));
}

// Split a float pair into bf16x2 hi + bf16x2 residual. lo half = x0 (lower k).
__device__ __forceinline__ void split2(float x0, float x1,
                                       uint32_t& h, uint32_t& l)
{
    uint32_t hp;
    asm("cvt.rn.bf16x2.f32 %0, %1, %2;" : "=r"(hp) : "f"(x1), "f"(x0));
    float h0 = __uint_as_float(hp << 16);
    float h1 = __uint_as_float(hp & 0xffff0000u);
    uint32_t lp;
    asm("cvt.rn.bf16x2.f32 %0, %1, %2;" : "=r"(lp) : "f"(x1 - h1), "f"(x0 - h0));
    h = hp;
    l = lp;
}

__device__ __forceinline__ void mma3(float d[4],
                                     const uint32_t ah[4], const uint32_t al[4],
                                     uint32_t bh0, uint32_t bl0,
                                     uint32_t bh1, uint32_t bl1)
{
    mma_bf16(d, ah, bh0, bh1);
    mma_bf16(d, ah, bl0, bl1);
    mma_bf16(d, al, bh0, bh1);
}

// ---------------------------------------------------------------------------
// One-shot W pre-split: g_wi[n*1024 + 2*kp + {0,1}] = split2(W[2kp][n], W[2kp+1][n])
// grid 384 x 256. Reads coalesced (nl fast).
// ---------------------------------------------------------------------------
__global__ __launch_bounds__(256) void wsplit_kernel(
    const float* __restrict__ Wq, const float* __restrict__ Wk,
    const float* __restrict__ Wv)
{
    const int idx = blockIdx.x * 256 + threadIdx.x;   // < 3*512*64
    const int nl = idx & 63;
    const int kp = (idx >> 6) & 511;
    const int m  = idx >> 15;
    const float* Wm = (m == 0) ? Wq : (m == 1 ? Wk : Wv);
    float x0 = Wm[(size_t)(2 * kp) * Hn + nl];
    float x1 = Wm[(size_t)(2 * kp + 1) * Hn + nl];
    uint32_t h, l;
    split2(x0, x1, h, l);
    const int n = m * 64 + nl;
    g_wi[n * 1024 + 2 * kp]     = h;
    g_wi[n * 1024 + 2 * kp + 1] = l;
}

// ---------------------------------------------------------------------------
// Projection: [16384,1024] x [1024,192] (+bias) -> g_q|g_k|g_v
// CTA = 64 rows x 192 cols, 8 warps (wm row-group, wn col-half). Chunk k=32.
// Interleaved (h,l) smem, stride 40 u32; double-buffered with reg prefetch.
// ---------------------------------------------------------------------------
#define SXI 40
#define SWI 40
#define PJ_X(b) ((b) * 64 * SXI)
#define PJ_W(b) (2 * 64 * SXI + (b) * 192 * SWI)
#define PJ_B    (2 * 64 * SXI + 2 * 192 * SWI)
#define PJ_TOT  (PJ_B + 192)

__global__ __launch_bounds__(256, 2) void proj_mma_kernel(
    const float* __restrict__ x,
    const float* __restrict__ bq, const float* __restrict__ bk,
    const float* __restrict__ bv)
{
    extern __shared__ uint32_t smu[];
    float* sB = (float*)(smu + PJ_B);

    const int tid  = threadIdx.x;
    const int warp = tid >> 5;
    const int lane = tid & 31;
    const int g    = lane >> 2;
    const int tg   = lane & 3;
    const int wm   = warp & 3;
    const int wn   = warp >> 2;
    const int row0 = blockIdx.x * 64;

    if (tid < 192) {
        const float* bb = (tid < 64) ? bq : (tid < 128 ? bk : bv);
        sB[tid] = bb[tid & 63];
    }

    // X loader: 2 units/thread: r = unit>>3 (0..63), c = unit&7 (float4 col)
    const int xr = tid >> 3;
    const int xc = tid & 7;
    // W loader: 6 units/thread: q = unit&7 (uint4 col), n = unit>>3 (0..191)

    float acc[12][4];
    #pragma unroll
    for (int t = 0; t < 12; t++)
        #pragma unroll
        for (int i = 0; i < 4; i++) acc[t][i] = 0.0f;

    float4 xreg[2];
    uint4  wreg[6];

    auto ldg_chunk = [&](int c) {
        const int k0 = c * 32;      // float k base
        const int kp0 = c * 16;     // pair base
        #pragma unroll
        for (int u = 0; u < 2; u++) {
            int r = xr + 32 * u;
            xreg[u] = *reinterpret_cast<const float4*>(
                &x[(size_t)(row0 + r) * En + k0 + 4 * xc]);
        }
        #pragma unroll
        for (int u = 0; u < 6; u++) {
            int unit = tid + 256 * u;        // < 1536
            int q = unit & 7, n = unit >> 3;
            wreg[u] = *reinterpret_cast<const uint4*>(
                &g_wi[n * 1024 + 2 * kp0 + 4 * q]);
        }
    };

    auto sts_chunk = [&](int buf) {
        uint32_t* sX = smu + PJ_X(buf);
        uint32_t* sW = smu + PJ_W(buf);
        #pragma unroll
        for (int u = 0; u < 2; u++) {
            int r = xr + 32 * u;
            uint4 o;
            split2(xreg[u].x, xreg[u].y, o.x, o.y);
            split2(xreg[u].z, xreg[u].w, o.z, o.w);
            *reinterpret_cast<uint4*>(&sX[r * SXI + 4 * xc]) = o;
        }
        #pragma unroll
        for (int u = 0; u < 6; u++) {
            int unit = tid + 256 * u;
            int q = unit & 7, n = unit >> 3;
            *reinterpret_cast<uint4*>(&sW[n * SWI + 4 * q]) = wreg[u];
        }
    };

    ldg_chunk(0);
    sts_chunk(0);
    __syncthreads();

    const int NCH = En / 32;
    for (int c = 0; c < NCH; c++) {
        const int buf = c & 1;
        if (c + 1 < NCH) ldg_chunk(c + 1);

        const uint32_t* sX = smu + PJ_X(buf);
        const uint32_t* sW = smu + PJ_W(buf);

        #pragma unroll
        for (int kk = 0; kk < 2; kk++) {
            uint32_t ah[4], al[4];
            const int a0 = (16 * wm + g) * SXI + 2 * (8 * kk + tg);
            uint2 u01 = *reinterpret_cast<const uint2*>(&sX[a0]);
            uint2 u23 = *reinterpret_cast<const uint2*>(&sX[a0 + 8]);
            uint2 u45 = *reinterpret_cast<const uint2*>(&sX[a0 + 8 * SXI]);
            uint2 u67 = *reinterpret_cast<const uint2*>(&sX[a0 + 8 * SXI + 8]);
            ah[0] = u01.x; al[0] = u01.y;
            ah[2] = u23.x; al[2] = u23.y;
            ah[1] = u45.x; al[1] = u45.y;
            ah[3] = u67.x; al[3] = u67.y;
            #pragma unroll
            for (int t = 0; t < 12; t++) {
                const int n = wn * 96 + 8 * t + g;
                const int b0 = n * SWI + 2 * (8 * kk + tg);
                uint2 bh = *reinterpret_cast<const uint2*>(&sW[b0]);
                uint2 bl = *reinterpret_cast<const uint2*>(&sW[b0 + 8]);
                mma3(acc[t], ah, al, bh.x, bh.y, bl.x, bl.y);
            }
        }

        if (c + 1 < NCH) sts_chunk(buf ^ 1);
        __syncthreads();
    }

    const int r0 = row0 + 16 * wm + g;
    #pragma unroll
    for (int t = 0; t < 12; t++) {
        const int col = wn * 96 + 8 * t + 2 * tg;
        float* dst = (col < 64) ? g_q : (col < 128 ? g_k : g_v);
        const int lcol = col & 63;
        float2 v0, v1;
        v0.x = acc[t][0] + sB[col];
        v0.y = acc[t][1] + sB[col + 1];
        v1.x = acc[t][2] + sB[col];
        v1.y = acc[t][3] + sB[col + 1];
        *reinterpret_cast<float2*>(&dst[(size_t)r0 * Hn + lcol]) = v0;
        *reinterpret_cast<float2*>(&dst[(size_t)(r0 + 8) * Hn + lcol]) = v1;
    }
}

// ---------------------------------------------------------------------------
// Flash attention, 4-way split-KV, 3xBF16, P overlaid on K smem. (as R8)
// ---------------------------------------------------------------------------
#define SKP 36
#define AT_KH 0
#define AT_KL (AT_KH + 64 * SKP)
#define AT_VH (AT_KL + 64 * SKP)
#define AT_VL (AT_VH + 64 * SKP)
#define AT_M  (AT_VL + 64 * SKP)
#define AT_TOT (AT_M + 64)

__global__ __launch_bounds__(128) void attn_mma_kernel(
    const int* __restrict__ mask)
{
    extern __shared__ uint32_t smu[];
    uint32_t* sKh = smu + AT_KH;
    uint32_t* sKl = smu + AT_KL;
    uint32_t* sVh = smu + AT_VH;
    uint32_t* sVl = smu + AT_VL;
    float*    sM  = (float*)(smu + AT_M);

    const int b    = blockIdx.y;
    const int qt   = (gridDim.x - 1) - blockIdx.x;
    const int z    = blockIdx.z;
    const int qbase = qt * 64;
    const int tid  = threadIdx.x;
    const int warp = tid >> 5;
    const int lane = tid & 31;
    const int g    = lane >> 2;
    const int tg   = lane & 3;
    const int wrow = warp * 16;

    const int nt  = qt + 1;
    const int jt_begin = (nt * z) / NSPLIT;
    const int jt_end   = (nt * (z + 1)) / NSPLIT;

    const float* qp = g_q + ((size_t)b * Sn + qbase + wrow) * Hn;
    const float* kp = g_k + (size_t)b * Sn * Hn;
    const float* vp = g_v + (size_t)b * Sn * Hn;

    uint32_t qh[4][4], ql[4][4];
    #pragma unroll
    for (int kc = 0; kc < 4; kc++) {
        const int kb = 16 * kc + 2 * tg;
        float2 q0 = *reinterpret_cast<const float2*>(&qp[(size_t)g * Hn + kb]);
        float2 q1 = *reinterpret_cast<const float2*>(&qp[(size_t)(g + 8) * Hn + kb]);
        float2 q2 = *reinterpret_cast<const float2*>(&qp[(size_t)g * Hn + kb + 8]);
        float2 q3 = *reinterpret_cast<const float2*>(&qp[(size_t)(g + 8) * Hn + kb + 8]);
        split2(q0.x * 0.125f, q0.y * 0.125f, qh[kc][0], ql[kc][0]);
        split2(q1.x * 0.125f, q1.y * 0.125f, qh[kc][1], ql[kc][1]);
        split2(q2.x * 0.125f, q2.y * 0.125f, qh[kc][2], ql[kc][2]);
        split2(q3.x * 0.125f, q3.y * 0.125f, qh[kc][3], ql[kc][3]);
    }

    float m0 = -1e30f, m1 = -1e30f, l0 = 0.0f, l1 = 0.0f;
    float o[8][4];
    #pragma unroll
    for (int t = 0; t < 8; t++)
        #pragma unroll
        for (int i = 0; i < 4; i++) o[t][i] = 0.0f;

    for (int jt = jt_begin; jt < jt_end; jt++) {
        const int kbase = jt * 64;

        #pragma unroll
        for (int u = 0; u < 8; u++) {
            int idx = tid + 128 * u;
            int r = idx >> 4, c = idx & 15;
            float4 kv = *reinterpret_cast<const float4*>(
                &kp[(size_t)(kbase + r) * Hn + 4 * c]);
            uint32_t h0, l0_, h1, l1_;
            split2(kv.x, kv.y, h0, l0_);
            split2(kv.z, kv.w, h1, l1_);
            uint2 hh; hh.x = h0; hh.y = h1;
            uint2 ll; ll.x = l0_; ll.y = l1_;
            *reinterpret_cast<uint2*>(&sKh[r * SKP + 2 * c]) = hh;
            *reinterpret_cast<uint2*>(&sKl[r * SKP + 2 * c]) = ll;
        }
        #pragma unroll
        for (int u = 0; u < 4; u++) {
            int idx = tid + 128 * u;
            int kvp = idx & 31;
            int c   = idx >> 5;
            float4 va = *reinterpret_cast<const float4*>(
                &vp[(size_t)(kbase + 2 * kvp) * Hn + 4 * c]);
            float4 vb = *reinterpret_cast<const float4*>(
                &vp[(size_t)(kbase + 2 * kvp + 1) * Hn + 4 * c]);
            const float* fa = (const float*)&va;
            const float* fb = (const float*)&vb;
            #pragma unroll
            for (int j = 0; j < 4; j++) {
                uint32_t h, l;
                split2(fa[j], fb[j], h, l);
                sVh[(4 * c + j) * SKP + kvp] = h;
                sVl[(4 * c + j) * SKP + kvp] = l;
            }
        }
        if (tid < 64)
            sM[tid] = (mask[b * Sn + kbase + tid] != 0) ? 0.0f : -1e30f;
        __syncthreads();

        float s[8][4];
        #pragma unroll
        for (int t = 0; t < 8; t++)
            #pragma unroll
            for (int i = 0; i < 4; i++) s[t][i] = 0.0f;

        #pragma unroll
        for (int t = 0; t < 8; t++) {
            const int krow = (8 * t + g) * SKP;
            #pragma unroll
            for (int kc = 0; kc < 4; kc++) {
                const int i0 = krow + 8 * kc + tg;
                mma3(s[t], qh[kc], ql[kc],
                     sKh[i0], sKl[i0], sKh[i0 + 4], sKl[i0 + 4]);
            }
        }

        const bool diag = (jt == qt);
        const int lrow0 = wrow + g;
        float rmax0 = -1e30f, rmax1 = -1e30f;
        #pragma unroll
        for (int t = 0; t < 8; t++) {
            const int c = 8 * t + 2 * tg;
            const float pa0 = sM[c], pa1 = sM[c + 1];
            s[t][0] += pa0; s[t][1] += pa1;
            s[t][2] += pa0; s[t][3] += pa1;
            if (diag) {
                if (c > lrow0)         s[t][0] = -1e30f;
                if (c + 1 > lrow0)     s[t][1] = -1e30f;
                if (c > lrow0 + 8)     s[t][2] = -1e30f;
                if (c + 1 > lrow0 + 8) s[t][3] = -1e30f;
            }
            rmax0 = fmaxf(rmax0, fmaxf(s[t][0], s[t][1]));
            rmax1 = fmaxf(rmax1, fmaxf(s[t][2], s[t][3]));
        }
        rmax0 = fmaxf(rmax0, __shfl_xor_sync(0xffffffffu, rmax0, 1));
        rmax0 = fmaxf(rmax0, __shfl_xor_sync(0xffffffffu, rmax0, 2));
        rmax1 = fmaxf(rmax1, __shfl_xor_sync(0xffffffffu, rmax1, 1));
        rmax1 = fmaxf(rmax1, __shfl_xor_sync(0xffffffffu, rmax1, 2));

        const float mn0 = fmaxf(m0, rmax0);
        const float mn1 = fmaxf(m1, rmax1);
        const float al0 = __expf(m0 - mn0);
        const float al1 = __expf(m1 - mn1);

        float p[8][4];
        float ps0 = 0.0f, ps1 = 0.0f;
        #pragma unroll
        for (int t = 0; t < 8; t++) {
            p[t][0] = __expf(s[t][0] - mn0);
            p[t][1] = __expf(s[t][1] - mn0);
            p[t][2] = __expf(s[t][2] - mn1);
            p[t][3] = __expf(s[t][3] - mn1);
            ps0 += p[t][0] + p[t][1];
            ps1 += p[t][2] + p[t][3];
        }
        __syncthreads();

        #pragma unroll
        for (int t = 0; t < 8; t++) {
            uint32_t h, l;
            split2(p[t][0], p[t][1], h, l);
            sKh[(wrow + g) * SKP + 4 * t + tg] = h;
            sKl[(wrow + g) * SKP + 4 * t + tg] = l;
            split2(p[t][2], p[t][3], h, l);
            sKh[(wrow + g + 8) * SKP + 4 * t + tg] = h;
            sKl[(wrow + g + 8) * SKP + 4 * t + tg] = l;
        }
        ps0 += __shfl_xor_sync(0xffffffffu, ps0, 1);
        ps0 += __shfl_xor_sync(0xffffffffu, ps0, 2);
        ps1 += __shfl_xor_sync(0xffffffffu, ps1, 1);
        ps1 += __shfl_xor_sync(0xffffffffu, ps1, 2);

        l0 = l0 * al0 + ps0;
        l1 = l1 * al1 + ps1;
        m0 = mn0;
        m1 = mn1;
        #pragma unroll
        for (int t = 0; t < 8; t++) {
            o[t][0] *= al0; o[t][1] *= al0;
            o[t][2] *= al1; o[t][3] *= al1;
        }
        __syncwarp();

        #pragma unroll
        for (int kc = 0; kc < 4; kc++) {
            uint32_t ah[4], al_[4];
            const int pr = (wrow + g) * SKP + 8 * kc + tg;
            ah[0] = sKh[pr];               al_[0] = sKl[pr];
            ah[1] = sKh[pr + 8 * SKP];     al_[1] = sKl[pr + 8 * SKP];
            ah[2] = sKh[pr + 4];           al_[2] = sKl[pr + 4];
            ah[3] = sKh[pr + 8 * SKP + 4]; al_[3] = sKl[pr + 8 * SKP + 4];
            #pragma unroll
            for (int t = 0; t < 8; t++) {
                const int i0 = (8 * t + g) * SKP + 8 * kc + tg;
                mma3(o[t], ah, al_,
                     sVh[i0], sVl[i0], sVh[i0 + 4], sVl[i0 + 4]);
            }
        }
        __syncthreads();
    }

    float* op = g_op + (size_t)z * Bn * Sn * Hn;
    float* ml = g_ml + (size_t)z * Bn * Sn * 2;
    const size_t row0 = (size_t)b * Sn + qbase + wrow + g;
    #pragma unroll
    for (int t = 0; t < 8; t++) {
        const int col = 8 * t + 2 * tg;
        float2 w0, w1;
        w0.x = o[t][0]; w0.y = o[t][1];
        w1.x = o[t][2]; w1.y = o[t][3];
        *reinterpret_cast<float2*>(&op[row0 * Hn + col]) = w0;
        *reinterpret_cast<float2*>(&op[(row0 + 8) * Hn + col]) = w1;
    }
    if (tg == 0) {
        ml[row0 * 2]           = m0;
        ml[row0 * 2 + 1]       = l0;
        ml[(row0 + 8) * 2]     = m1;
        ml[(row0 + 8) * 2 + 1] = l1;
    }
}

// ---------------------------------------------------------------------------
// Merge the 4 KV splits
// ---------------------------------------------------------------------------
__global__ __launch_bounds__(256) void merge_kernel(float* __restrict__ out)
{
    const int tid = threadIdx.x;
    const int row = blockIdx.x * 16 + (tid >> 4);
    const int c4  = (tid & 15) * 4;

    float mz[NSPLIT], lz[NSPLIT];
    float m = -1e30f;
    #pragma unroll
    for (int zz = 0; zz < NSPLIT; zz++) {
        mz[zz] = g_ml[(size_t)zz * Bn * Sn * 2 + row * 2];
        lz[zz] = g_ml[(size_t)zz * Bn * Sn * 2 + row * 2 + 1];
        m = fmaxf(m, mz[zz]);
    }
    float denom = 0.0f;
    float w[NSPLIT];
    #pragma unroll
    for (int zz = 0; zz < NSPLIT; zz++) {
        w[zz] = __expf(mz[zz] - m);
        denom += w[zz] * lz[zz];
    }
    const float inv = 1.0f / denom;

    float4 r;
    r.x = 0.0f; r.y = 0.0f; r.z = 0.0f; r.w = 0.0f;
    #pragma unroll
    for (int zz = 0; zz < NSPLIT; zz++) {
        float4 a = *reinterpret_cast<const float4*>(
            &g_op[(size_t)zz * Bn * Sn * Hn + (size_t)row * Hn + c4]);
        r.x += w[zz] * a.x;
        r.y += w[zz] * a.y;
        r.z += w[zz] * a.z;
        r.w += w[zz] * a.w;
    }
    r.x *= inv; r.y *= inv; r.z *= inv; r.w *= inv;
    *reinterpret_cast<float4*>(&out[(size_t)row * Hn + c4]) = r;
}

extern "C" void kernel_launch(void* const* d_in, const int* in_sizes, int n_in,
                              void* d_out, int out_size)
{
    const float* x    = (const float*)d_in[0];
    const int*   mask = (const int*)d_in[1];
    const float* Wq   = (const float*)d_in[2];
    const float* bq   = (const float*)d_in[3];
    const float* Wk   = (const float*)d_in[4];
    const float* bk   = (const float*)d_in[5];
    const float* Wv   = (const float*)d_in[6];
    const float* bv   = (const float*)d_in[7];
    float* out = (float*)d_out;

    cudaFuncSetAttribute(proj_mma_kernel,
                         cudaFuncAttributeMaxDynamicSharedMemorySize,
                         PJ_TOT * (int)sizeof(uint32_t));
    cudaFuncSetAttribute(attn_mma_kernel,
                         cudaFuncAttributeMaxDynamicSharedMemorySize,
                         AT_TOT * (int)sizeof(uint32_t));

    wsplit_kernel<<<384, 256>>>(Wq, Wk, Wv);

    proj_mma_kernel<<<Bn * Sn / 64, 256, PJ_TOT * sizeof(uint32_t)>>>(
        x, bq, bk, bv);

    dim3 gattn(Sn / 64, Bn, NSPLIT);
    attn_mma_kernel<<<gattn, 128, AT_TOT * sizeof(uint32_t)>>>(mask);

    merge_kernel<<<Bn * Sn / 16, 256>>>(out);
}

// round 11
// speedup vs baseline: 1.3188x; 1.0278x over previous
#include <cuda_runtime.h>
#include <math.h>
#include <cstdint>

#define Bn 8
#define Sn 2048
#define En 1024
#define Hn 64
#define NSPLIT 4

// Scratch: v [B,S,H] fp32; q,k,v pre-split bf16-pair forms; partials; W split
__device__ float g_v[Bn * Sn * Hn];
__device__ uint32_t g_qi[Bn * Sn * 64];   // q: (h,l) pairs along h, PRE-SCALED
__device__ uint32_t g_ki[Bn * Sn * 64];   // k: (h,l) pairs along h
__device__ uint32_t g_vi[Bn * 64 * 2048]; // v: [b][h][kvpair] (h,l) pairs along kv
__device__ float g_op[NSPLIT * Bn * Sn * Hn];
__device__ float g_ml[NSPLIT * Bn * Sn * 2];
__device__ uint32_t g_wi[192 * 1024];     // W: (h,l) pairs along k

// m16n8k16 bf16 mma: D += A*B, fp32 accumulate.
__device__ __forceinline__ void mma_bf16(float d[4], const uint32_t a[4],
                                         uint32_t b0, uint32_t b1)
{
    asm volatile(
        "mma.sync.aligned.m16n8k16.row.col.f32.bf16.bf16.f32 "
        "{%0,%1,%2,%3}, {%4,%5,%6,%7}, {%8,%9}, {%0,%1,%2,%3};"
        : "+f"(d[0]), "+f"(d[1]), "+f"(d[2]), "+f"(d[3])
        : "r"(a[0]), "r"(a[1]), "r"(a[2]), "r"(a[3]), "r"(b0), "r"(b1));
}

__device__ __forceinline__ void split2(float x0, float x1,
                                       uint32_t& h, uint32_t& l)
{
    uint32_t hp;
    asm("cvt.rn.bf16x2.f32 %0, %1, %2;" : "=r"(hp) : "f"(x1), "f"(x0));
    float h0 = __uint_as_float(hp << 16);
    float h1 = __uint_as_float(hp & 0xffff0000u);
    uint32_t lp;
    asm("cvt.rn.bf16x2.f32 %0, %1, %2;" : "=r"(lp) : "f"(x1 - h1), "f"(x0 - h0));
    h = hp;
    l = lp;
}

__device__ __forceinline__ void mma3(float d[4],
                                     const uint32_t ah[4], const uint32_t al[4],
                                     uint32_t bh0, uint32_t bl0,
                                     uint32_t bh1, uint32_t bl1)
{
    mma_bf16(d, ah, bh0, bh1);
    mma_bf16(d, ah, bl0, bl1);
    mma_bf16(d, al, bh0, bh1);
}

// ---------------------------------------------------------------------------
// One-shot W pre-split
// ---------------------------------------------------------------------------
__global__ __launch_bounds__(256) void wsplit_kernel(
    const float* __restrict__ Wq, const float* __restrict__ Wk,
    const float* __restrict__ Wv)
{
    const int idx = blockIdx.x * 256 + threadIdx.x;
    const int nl = idx & 63;
    const int kp = (idx >> 6) & 511;
    const int m  = idx >> 15;
    const float* Wm = (m == 0) ? Wq : (m == 1 ? Wk : Wv);
    float x0 = Wm[(size_t)(2 * kp) * Hn + nl];
    float x1 = Wm[(size_t)(2 * kp + 1) * Hn + nl];
    uint32_t h, l;
    split2(x0, x1, h, l);
    const int n = m * 64 + nl;
    g_wi[n * 1024 + 2 * kp]     = h;
    g_wi[n * 1024 + 2 * kp + 1] = l;
}

// ---------------------------------------------------------------------------
// One-shot V pre-split+transpose: g_vi[b][h][P] = split2(V[2P][h], V[2P+1][h])
// ---------------------------------------------------------------------------
__global__ __launch_bounds__(256) void vsplit_kernel()
{
    __shared__ float t[64][65];
    const int b  = blockIdx.y;
    const int kbase = blockIdx.x * 64;
    const int tid = threadIdx.x;

    #pragma unroll
    for (int u = 0; u < 16; u++) {
        int idx = tid + 256 * u;
        int kv = idx >> 6, h = idx & 63;
        t[kv][h] = g_v[((size_t)b * Sn + kbase + kv) * Hn + h];
    }
    __syncthreads();
    #pragma unroll
    for (int u = 0; u < 8; u++) {
        int idx = tid + 256 * u;
        int h = idx >> 5, Pl = idx & 31;
        uint32_t hh, ll;
        split2(t[2 * Pl][h], t[2 * Pl + 1][h], hh, ll);
        uint2 o; o.x = hh; o.y = ll;
        *reinterpret_cast<uint2*>(
            &g_vi[((size_t)(b * 64 + h)) * 2048 + kbase + 2 * Pl]) = o;
    }
}

// ---------------------------------------------------------------------------
// Projection: epilogue writes q (scaled+split) / k (split) / v fp32
// ---------------------------------------------------------------------------
#define SXI 40
#define SWI 40
#define PJ_X(b) ((b) * 64 * SXI)
#define PJ_W(b) (2 * 64 * SXI + (b) * 192 * SWI)
#define PJ_B    (2 * 64 * SXI + 2 * 192 * SWI)
#define PJ_TOT  (PJ_B + 192)

__global__ __launch_bounds__(256, 2) void proj_mma_kernel(
    const float* __restrict__ x,
    const float* __restrict__ bq, const float* __restrict__ bk,
    const float* __restrict__ bv)
{
    extern __shared__ uint32_t smu[];
    float* sB = (float*)(smu + PJ_B);

    const int tid  = threadIdx.x;
    const int warp = tid >> 5;
    const int lane = tid & 31;
    const int g    = lane >> 2;
    const int tg   = lane & 3;
    const int wm   = warp & 3;
    const int wn   = warp >> 2;
    const int row0 = blockIdx.x * 64;

    if (tid < 192) {
        const float* bb = (tid < 64) ? bq : (tid < 128 ? bk : bv);
        sB[tid] = bb[tid & 63];
    }

    const int xr = tid >> 3;
    const int xc = tid & 7;

    float acc[12][4];
    #pragma unroll
    for (int t = 0; t < 12; t++)
        #pragma unroll
        for (int i = 0; i < 4; i++) acc[t][i] = 0.0f;

    float4 xreg[2];
    uint4  wreg[6];

    auto ldg_chunk = [&](int c) {
        const int k0 = c * 32;
        const int kp0 = c * 16;
        #pragma unroll
        for (int u = 0; u < 2; u++) {
            int r = xr + 32 * u;
            xreg[u] = *reinterpret_cast<const float4*>(
                &x[(size_t)(row0 + r) * En + k0 + 4 * xc]);
        }
        #pragma unroll
        for (int u = 0; u < 6; u++) {
            int unit = tid + 256 * u;
            int q = unit & 7, n = unit >> 3;
            wreg[u] = *reinterpret_cast<const uint4*>(
                &g_wi[n * 1024 + 2 * kp0 + 4 * q]);
        }
    };

    auto sts_chunk = [&](int buf) {
        uint32_t* sX = smu + PJ_X(buf);
        uint32_t* sW = smu + PJ_W(buf);
        #pragma unroll
        for (int u = 0; u < 2; u++) {
            int r = xr + 32 * u;
            uint4 o;
            split2(xreg[u].x, xreg[u].y, o.x, o.y);
            split2(xreg[u].z, xreg[u].w, o.z, o.w);
            *reinterpret_cast<uint4*>(&sX[r * SXI + 4 * xc]) = o;
        }
        #pragma unroll
        for (int u = 0; u < 6; u++) {
            int unit = tid + 256 * u;
            int q = unit & 7, n = unit >> 3;
            *reinterpret_cast<uint4*>(&sW[n * SWI + 4 * q]) = wreg[u];
        }
    };

    ldg_chunk(0);
    sts_chunk(0);
    __syncthreads();

    const int NCH = En / 32;
    for (int c = 0; c < NCH; c++) {
        const int buf = c & 1;
        if (c + 1 < NCH) ldg_chunk(c + 1);

        const uint32_t* sX = smu + PJ_X(buf);
        const uint32_t* sW = smu + PJ_W(buf);

        #pragma unroll
        for (int kk = 0; kk < 2; kk++) {
            uint32_t ah[4], al[4];
            const int a0 = (16 * wm + g) * SXI + 2 * (8 * kk + tg);
            uint2 u01 = *reinterpret_cast<const uint2*>(&sX[a0]);
            uint2 u23 = *reinterpret_cast<const uint2*>(&sX[a0 + 8]);
            uint2 u45 = *reinterpret_cast<const uint2*>(&sX[a0 + 8 * SXI]);
            uint2 u67 = *reinterpret_cast<const uint2*>(&sX[a0 + 8 * SXI + 8]);
            ah[0] = u01.x; al[0] = u01.y;
            ah[2] = u23.x; al[2] = u23.y;
            ah[1] = u45.x; al[1] = u45.y;
            ah[3] = u67.x; al[3] = u67.y;
            #pragma unroll
            for (int t = 0; t < 12; t++) {
                const int n = wn * 96 + 8 * t + g;
                const int b0 = n * SWI + 2 * (8 * kk + tg);
                uint2 bh = *reinterpret_cast<const uint2*>(&sW[b0]);
                uint2 bl = *reinterpret_cast<const uint2*>(&sW[b0 + 8]);
                mma3(acc[t], ah, al, bh.x, bh.y, bl.x, bl.y);
            }
        }

        if (c + 1 < NCH) sts_chunk(buf ^ 1);
        __syncthreads();
    }

    const int r0 = row0 + 16 * wm + g;
    #pragma unroll
    for (int t = 0; t < 12; t++) {
        const int col = wn * 96 + 8 * t + 2 * tg;   // even
        float a0 = acc[t][0] + sB[col];
        float a1 = acc[t][1] + sB[col + 1];
        float a2 = acc[t][2] + sB[col];
        float a3 = acc[t][3] + sB[col + 1];
        if (col < 64) {
            uint2 o;
            split2(a0 * 0.125f, a1 * 0.125f, o.x, o.y);
            *reinterpret_cast<uint2*>(&g_qi[(size_t)r0 * 64 + col]) = o;
            split2(a2 * 0.125f, a3 * 0.125f, o.x, o.y);
            *reinterpret_cast<uint2*>(&g_qi[(size_t)(r0 + 8) * 64 + col]) = o;
        } else if (col < 128) {
            uint2 o;
            split2(a0, a1, o.x, o.y);
            *reinterpret_cast<uint2*>(&g_ki[(size_t)r0 * 64 + col - 64]) = o;
            split2(a2, a3, o.x, o.y);
            *reinterpret_cast<uint2*>(&g_ki[(size_t)(r0 + 8) * 64 + col - 64]) = o;
        } else {
            const int lcol = col - 128;
            float2 v0, v1;
            v0.x = a0; v0.y = a1;
            v1.x = a2; v1.y = a3;
            *reinterpret_cast<float2*>(&g_v[(size_t)r0 * Hn + lcol]) = v0;
            *reinterpret_cast<float2*>(&g_v[(size_t)(r0 + 8) * Hn + lcol]) = v1;
        }
    }
}

// ---------------------------------------------------------------------------
// Flash attention, 4-way split-KV, 3xBF16. Pre-split operands, pure-copy
// loaders. K/P rows are 64 u32 -> stride 72 (FIX: was 40, rows overlapped).
// ---------------------------------------------------------------------------
#define SKI 72
#define SVI 72
#define AT_K 0
#define AT_V (AT_K + 64 * SKI)
#define AT_M (AT_V + 64 * SVI)
#define AT_TOT (AT_M + 64)

__global__ __launch_bounds__(128) void attn_mma_kernel(
    const int* __restrict__ mask)
{
    extern __shared__ uint32_t smu[];
    uint32_t* sK = smu + AT_K;    // doubles as P after S-MMA
    uint32_t* sV = smu + AT_V;
    float*    sM = (float*)(smu + AT_M);

    const int b    = blockIdx.y;
    const int qt   = (gridDim.x - 1) - blockIdx.x;
    const int z    = blockIdx.z;
    const int qbase = qt * 64;
    const int tid  = threadIdx.x;
    const int warp = tid >> 5;
    const int lane = tid & 31;
    const int g    = lane >> 2;
    const int tg   = lane & 3;
    const int wrow = warp * 16;

    const int nt  = qt + 1;
    const int jt_begin = (nt * z) / NSPLIT;
    const int jt_end   = (nt * (z + 1)) / NSPLIT;

    const uint32_t* qip = g_qi + ((size_t)b * Sn + qbase + wrow) * 64;
    const uint32_t* kip = g_ki + (size_t)b * Sn * 64;
    const uint32_t* vip = g_vi + (size_t)b * 64 * 2048;

    uint32_t qh[4][4], ql[4][4];
    #pragma unroll
    for (int kc = 0; kc < 4; kc++) {
        const int hp = 8 * kc + tg;
        uint2 a0 = *reinterpret_cast<const uint2*>(&qip[(size_t)g * 64 + 2 * hp]);
        uint2 a1 = *reinterpret_cast<const uint2*>(&qip[(size_t)(g + 8) * 64 + 2 * hp]);
        uint2 a2 = *reinterpret_cast<const uint2*>(&qip[(size_t)g * 64 + 2 * hp + 8]);
        uint2 a3 = *reinterpret_cast<const uint2*>(&qip[(size_t)(g + 8) * 64 + 2 * hp + 8]);
        qh[kc][0] = a0.x; ql[kc][0] = a0.y;
        qh[kc][1] = a1.x; ql[kc][1] = a1.y;
        qh[kc][2] = a2.x; ql[kc][2] = a2.y;
        qh[kc][3] = a3.x; ql[kc][3] = a3.y;
    }

    float m0 = -1e30f, m1 = -1e30f, l0 = 0.0f, l1 = 0.0f;
    float o[8][4];
    #pragma unroll
    for (int t = 0; t < 8; t++)
        #pragma unroll
        for (int i = 0; i < 4; i++) o[t][i] = 0.0f;

    for (int jt = jt_begin; jt < jt_end; jt++) {
        const int kbase = jt * 64;

        #pragma unroll
        for (int u = 0; u < 8; u++) {
            int idx = tid + 128 * u;
            int r = idx >> 4, q4 = idx & 15;
            uint4 v = *reinterpret_cast<const uint4*>(
                &kip[(size_t)(kbase + r) * 64 + 4 * q4]);
            *reinterpret_cast<uint4*>(&sK[r * SKI + 4 * q4]) = v;
        }
        #pragma unroll
        for (int u = 0; u < 8; u++) {
            int idx = tid + 128 * u;
            int h = idx >> 4, q4 = idx & 15;
            uint4 v = *reinterpret_cast<const uint4*>(
                &vip[(size_t)h * 2048 + kbase + 4 * q4]);
            *reinterpret_cast<uint4*>(&sV[h * SVI + 4 * q4]) = v;
        }
        if (tid < 64)
            sM[tid] = (mask[b * Sn + kbase + tid] != 0) ? 0.0f : -1e30f;
        __syncthreads();

        // S = Q * K^T
        float s[8][4];
        #pragma unroll
        for (int t = 0; t < 8; t++)
            #pragma unroll
            for (int i = 0; i < 4; i++) s[t][i] = 0.0f;

        #pragma unroll
        for (int t = 0; t < 8; t++) {
            const int krow = (8 * t + g) * SKI;
            #pragma unroll
            for (int kc = 0; kc < 4; kc++) {
                uint2 b0 = *reinterpret_cast<const uint2*>(
                    &sK[krow + 2 * (8 * kc + tg)]);
                uint2 b1 = *reinterpret_cast<const uint2*>(
                    &sK[krow + 2 * (8 * kc + tg) + 8]);
                mma3(s[t], qh[kc], ql[kc], b0.x, b0.y, b1.x, b1.y);
            }
        }

        // Mask + online softmax
        const bool diag = (jt == qt);
        const int lrow0 = wrow + g;
        float rmax0 = -1e30f, rmax1 = -1e30f;
        #pragma unroll
        for (int t = 0; t < 8; t++) {
            const int c = 8 * t + 2 * tg;
            const float pa0 = sM[c], pa1 = sM[c + 1];
            s[t][0] += pa0; s[t][1] += pa1;
            s[t][2] += pa0; s[t][3] += pa1;
            if (diag) {
                if (c > lrow0)         s[t][0] = -1e30f;
                if (c + 1 > lrow0)     s[t][1] = -1e30f;
                if (c > lrow0 + 8)     s[t][2] = -1e30f;
                if (c + 1 > lrow0 + 8) s[t][3] = -1e30f;
            }
            rmax0 = fmaxf(rmax0, fmaxf(s[t][0], s[t][1]));
            rmax1 = fmaxf(rmax1, fmaxf(s[t][2], s[t][3]));
        }
        rmax0 = fmaxf(rmax0, __shfl_xor_sync(0xffffffffu, rmax0, 1));
        rmax0 = fmaxf(rmax0, __shfl_xor_sync(0xffffffffu, rmax0, 2));
        rmax1 = fmaxf(rmax1, __shfl_xor_sync(0xffffffffu, rmax1, 1));
        rmax1 = fmaxf(rmax1, __shfl_xor_sync(0xffffffffu, rmax1, 2));

        const float mn0 = fmaxf(m0, rmax0);
        const float mn1 = fmaxf(m1, rmax1);
        const float al0 = __expf(m0 - mn0);
        const float al1 = __expf(m1 - mn1);

        float p[8][4];
        float ps0 = 0.0f, ps1 = 0.0f;
        #pragma unroll
        for (int t = 0; t < 8; t++) {
            p[t][0] = __expf(s[t][0] - mn0);
            p[t][1] = __expf(s[t][1] - mn0);
            p[t][2] = __expf(s[t][2] - mn1);
            p[t][3] = __expf(s[t][3] - mn1);
            ps0 += p[t][0] + p[t][1];
            ps1 += p[t][2] + p[t][3];
        }
        __syncthreads();   // sK dead -> overlay P

        #pragma unroll
        for (int t = 0; t < 8; t++) {
            uint2 o2;
            split2(p[t][0], p[t][1], o2.x, o2.y);
            *reinterpret_cast<uint2*>(
                &sK[(wrow + g) * SKI + 2 * (4 * t + tg)]) = o2;
            split2(p[t][2], p[t][3], o2.x, o2.y);
            *reinterpret_cast<uint2*>(
                &sK[(wrow + g + 8) * SKI + 2 * (4 * t + tg)]) = o2;
        }
        ps0 += __shfl_xor_sync(0xffffffffu, ps0, 1);
        ps0 += __shfl_xor_sync(0xffffffffu, ps0, 2);
        ps1 += __shfl_xor_sync(0xffffffffu, ps1, 1);
        ps1 += __shfl_xor_sync(0xffffffffu, ps1, 2);

        l0 = l0 * al0 + ps0;
        l1 = l1 * al1 + ps1;
        m0 = mn0;
        m1 = mn1;
        #pragma unroll
        for (int t = 0; t < 8; t++) {
            o[t][0] *= al0; o[t][1] *= al0;
            o[t][2] *= al1; o[t][3] *= al1;
        }
        __syncwarp();

        // O += P * V
        #pragma unroll
        for (int kc = 0; kc < 4; kc++) {
            uint32_t ah[4], al_[4];
            const int pr = (wrow + g) * SKI + 2 * (8 * kc + tg);
            uint2 a0 = *reinterpret_cast<const uint2*>(&sK[pr]);
            uint2 a1 = *reinterpret_cast<const uint2*>(&sK[pr + 8 * SKI]);
            uint2 a2 = *reinterpret_cast<const uint2*>(&sK[pr + 8]);
            uint2 a3 = *reinterpret_cast<const uint2*>(&sK[pr + 8 * SKI + 8]);
            ah[0] = a0.x; al_[0] = a0.y;
            ah[1] = a1.x; al_[1] = a1.y;
            ah[2] = a2.x; al_[2] = a2.y;
            ah[3] = a3.x; al_[3] = a3.y;
            #pragma unroll
            for (int t = 0; t < 8; t++) {
                const int vr = (8 * t + g) * SVI + 2 * (8 * kc + tg);
                uint2 b0 = *reinterpret_cast<const uint2*>(&sV[vr]);
                uint2 b1 = *reinterpret_cast<const uint2*>(&sV[vr + 8]);
                mma3(o[t], ah, al_, b0.x, b0.y, b1.x, b1.y);
            }
        }
        __syncthreads();
    }

    float* op = g_op + (size_t)z * Bn * Sn * Hn;
    float* ml = g_ml + (size_t)z * Bn * Sn * 2;
    const size_t row0 = (size_t)b * Sn + qbase + wrow + g;
    #pragma unroll
    for (int t = 0; t < 8; t++) {
        const int col = 8 * t + 2 * tg;
        float2 w0, w1;
        w0.x = o[t][0]; w0.y = o[t][1];
        w1.x = o[t][2]; w1.y = o[t][3];
        *reinterpret_cast<float2*>(&op[row0 * Hn + col]) = w0;
        *reinterpret_cast<float2*>(&op[(row0 + 8) * Hn + col]) = w1;
    }
    if (tg == 0) {
        ml[row0 * 2]           = m0;
        ml[row0 * 2 + 1]       = l0;
        ml[(row0 + 8) * 2]     = m1;
        ml[(row0 + 8) * 2 + 1] = l1;
    }
}

// ---------------------------------------------------------------------------
// Merge the 4 KV splits
// ---------------------------------------------------------------------------
__global__ __launch_bounds__(256) void merge_kernel(float* __restrict__ out)
{
    const int tid = threadIdx.x;
    const int row = blockIdx.x * 16 + (tid >> 4);
    const int c4  = (tid & 15) * 4;

    float mz[NSPLIT], lz[NSPLIT];
    float m = -1e30f;
    #pragma unroll
    for (int zz = 0; zz < NSPLIT; zz++) {
        mz[zz] = g_ml[(size_t)zz * Bn * Sn * 2 + row * 2];
        lz[zz] = g_ml[(size_t)zz * Bn * Sn * 2 + row * 2 + 1];
        m = fmaxf(m, mz[zz]);
    }
    float denom = 0.0f;
    float w[NSPLIT];
    #pragma unroll
    for (int zz = 0; zz < NSPLIT; zz++) {
        w[zz] = __expf(mz[zz] - m);
        denom += w[zz] * lz[zz];
    }
    const float inv = 1.0f / denom;

    float4 r;
    r.x = 0.0f; r.y = 0.0f; r.z = 0.0f; r.w = 0.0f;
    #pragma unroll
    for (int zz = 0; zz < NSPLIT; zz++) {
        float4 a = *reinterpret_cast<const float4*>(
            &g_op[(size_t)zz * Bn * Sn * Hn + (size_t)row * Hn + c4]);
        r.x += w[zz] * a.x;
        r.y += w[zz] * a.y;
        r.z += w[zz] * a.z;
        r.w += w[zz] * a.w;
    }
    r.x *= inv; r.y *= inv; r.z *= inv; r.w *= inv;
    *reinterpret_cast<float4*>(&out[(size_t)row * Hn + c4]) = r;
}

extern "C" void kernel_launch(void* const* d_in, const int* in_sizes, int n_in,
                              void* d_out, int out_size)
{
    const float* x    = (const float*)d_in[0];
    const int*   mask = (const int*)d_in[1];
    const float* Wq   = (const float*)d_in[2];
    const float* bq   = (const float*)d_in[3];
    const float* Wk   = (const float*)d_in[4];
    const float* bk   = (const float*)d_in[5];
    const float* Wv   = (const float*)d_in[6];
    const float* bv   = (const float*)d_in[7];
    float* out = (float*)d_out;

    cudaFuncSetAttribute(proj_mma_kernel,
                         cudaFuncAttributeMaxDynamicSharedMemorySize,
                         PJ_TOT * (int)sizeof(uint32_t));
    cudaFuncSetAttribute(attn_mma_kernel,
                         cudaFuncAttributeMaxDynamicSharedMemorySize,
                         AT_TOT * (int)sizeof(uint32_t));

    wsplit_kernel<<<384, 256>>>(Wq, Wk, Wv);

    proj_mma_kernel<<<Bn * Sn / 64, 256, PJ_TOT * sizeof(uint32_t)>>>(
        x, bq, bk, bv);

    dim3 gvs(Sn / 64, Bn);
    vsplit_kernel<<<gvs, 256>>>();

    dim3 gattn(Sn / 64, Bn, NSPLIT);
    attn_mma_kernel<<<gattn, 128, AT_TOT * sizeof(uint32_t)>>>(mask);

    merge_kernel<<<Bn * Sn / 16, 256>>>(out);
}

// round 12
// speedup vs baseline: 1.3526x; 1.0256x over previous
#include <cuda_runtime.h>
#include <math.h>
#include <cstdint>

#define Bn 8
#define Sn 2048
#define En 1024
#define Hn 64
#define NSPLIT 4

// Scratch: v [B,S,H] fp32; q,k,v pre-split bf16-pair forms; partials; W split
__device__ float g_v[Bn * Sn * Hn];
__device__ uint32_t g_qi[Bn * Sn * 64];   // q: (h,l) pairs along h, PRE-SCALED
__device__ uint32_t g_ki[Bn * Sn * 64];   // k: (h,l) pairs along h
__device__ uint32_t g_vi[Bn * 64 * 2048]; // v: [b][h][kvpair] (h,l) pairs along kv
__device__ float g_op[NSPLIT * Bn * Sn * Hn];
__device__ float g_ml[NSPLIT * Bn * Sn * 2];
__device__ uint32_t g_wi[192 * 1024];     // W: (h,l) pairs along k

__device__ __forceinline__ uint32_t smem_u32(const void* p) {
    uint32_t a;
    asm("{ .reg .u64 t; cvta.to.shared.u64 t, %1; cvt.u32.u64 %0, t; }"
        : "=r"(a) : "l"(p));
    return a;
}

#define CP16(dst, src) \
    asm volatile("cp.async.cg.shared.global [%0], [%1], 16;" \
                 :: "r"(dst), "l"(src) : "memory")
#define CP_COMMIT() asm volatile("cp.async.commit_group;" ::: "memory")
#define CP_WAIT0()  asm volatile("cp.async.wait_group 0;" ::: "memory")

// m16n8k16 bf16 mma: D += A*B, fp32 accumulate.
__device__ __forceinline__ void mma_bf16(float d[4], const uint32_t a[4],
                                         uint32_t b0, uint32_t b1)
{
    asm volatile(
        "mma.sync.aligned.m16n8k16.row.col.f32.bf16.bf16.f32 "
        "{%0,%1,%2,%3}, {%4,%5,%6,%7}, {%8,%9}, {%0,%1,%2,%3};"
        : "+f"(d[0]), "+f"(d[1]), "+f"(d[2]), "+f"(d[3])
        : "r"(a[0]), "r"(a[1]), "r"(a[2]), "r"(a[3]), "r"(b0), "r"(b1));
}

__device__ __forceinline__ void split2(float x0, float x1,
                                       uint32_t& h, uint32_t& l)
{
    uint32_t hp;
    asm("cvt.rn.bf16x2.f32 %0, %1, %2;" : "=r"(hp) : "f"(x1), "f"(x0));
    float h0 = __uint_as_float(hp << 16);
    float h1 = __uint_as_float(hp & 0xffff0000u);
    uint32_t lp;
    asm("cvt.rn.bf16x2.f32 %0, %1, %2;" : "=r"(lp) : "f"(x1 - h1), "f"(x0 - h0));
    h = hp;
    l = lp;
}

__device__ __forceinline__ void mma3(float d[4],
                                     const uint32_t ah[4], const uint32_t al[4],
                                     uint32_t bh0, uint32_t bl0,
                                     uint32_t bh1, uint32_t bl1)
{
    mma_bf16(d, ah, bh0, bh1);
    mma_bf16(d, ah, bl0, bl1);
    mma_bf16(d, al, bh0, bh1);
}

// ---------------------------------------------------------------------------
// One-shot W pre-split
// ---------------------------------------------------------------------------
__global__ __launch_bounds__(256) void wsplit_kernel(
    const float* __restrict__ Wq, const float* __restrict__ Wk,
    const float* __restrict__ Wv)
{
    const int idx = blockIdx.x * 256 + threadIdx.x;
    const int nl = idx & 63;
    const int kp = (idx >> 6) & 511;
    const int m  = idx >> 15;
    const float* Wm = (m == 0) ? Wq : (m == 1 ? Wk : Wv);
    float x0 = Wm[(size_t)(2 * kp) * Hn + nl];
    float x1 = Wm[(size_t)(2 * kp + 1) * Hn + nl];
    uint32_t h, l;
    split2(x0, x1, h, l);
    const int n = m * 64 + nl;
    g_wi[n * 1024 + 2 * kp]     = h;
    g_wi[n * 1024 + 2 * kp + 1] = l;
}

// ---------------------------------------------------------------------------
// One-shot V pre-split+transpose
// ---------------------------------------------------------------------------
__global__ __launch_bounds__(256) void vsplit_kernel()
{
    __shared__ float t[64][65];
    const int b  = blockIdx.y;
    const int kbase = blockIdx.x * 64;
    const int tid = threadIdx.x;

    #pragma unroll
    for (int u = 0; u < 16; u++) {
        int idx = tid + 256 * u;
        int kv = idx >> 6, h = idx & 63;
        t[kv][h] = g_v[((size_t)b * Sn + kbase + kv) * Hn + h];
    }
    __syncthreads();
    #pragma unroll
    for (int u = 0; u < 8; u++) {
        int idx = tid + 256 * u;
        int h = idx >> 5, Pl = idx & 31;
        uint32_t hh, ll;
        split2(t[2 * Pl][h], t[2 * Pl + 1][h], hh, ll);
        uint2 o; o.x = hh; o.y = ll;
        *reinterpret_cast<uint2*>(
            &g_vi[((size_t)(b * 64 + h)) * 2048 + kbase + 2 * Pl]) = o;
    }
}

// ---------------------------------------------------------------------------
// Projection (unchanged from R11)
// ---------------------------------------------------------------------------
#define SXI 40
#define SWI 40
#define PJ_X(b) ((b) * 64 * SXI)
#define PJ_W(b) (2 * 64 * SXI + (b) * 192 * SWI)
#define PJ_B    (2 * 64 * SXI + 2 * 192 * SWI)
#define PJ_TOT  (PJ_B + 192)

__global__ __launch_bounds__(256, 2) void proj_mma_kernel(
    const float* __restrict__ x,
    const float* __restrict__ bq, const float* __restrict__ bk,
    const float* __restrict__ bv)
{
    extern __shared__ uint32_t smu[];
    float* sB = (float*)(smu + PJ_B);

    const int tid  = threadIdx.x;
    const int warp = tid >> 5;
    const int lane = tid & 31;
    const int g    = lane >> 2;
    const int tg   = lane & 3;
    const int wm   = warp & 3;
    const int wn   = warp >> 2;
    const int row0 = blockIdx.x * 64;

    if (tid < 192) {
        const float* bb = (tid < 64) ? bq : (tid < 128 ? bk : bv);
        sB[tid] = bb[tid & 63];
    }

    const int xr = tid >> 3;
    const int xc = tid & 7;

    float acc[12][4];
    #pragma unroll
    for (int t = 0; t < 12; t++)
        #pragma unroll
        for (int i = 0; i < 4; i++) acc[t][i] = 0.0f;

    float4 xreg[2];
    uint4  wreg[6];

    auto ldg_chunk = [&](int c) {
        const int k0 = c * 32;
        const int kp0 = c * 16;
        #pragma unroll
        for (int u = 0; u < 2; u++) {
            int r = xr + 32 * u;
            xreg[u] = *reinterpret_cast<const float4*>(
                &x[(size_t)(row0 + r) * En + k0 + 4 * xc]);
        }
        #pragma unroll
        for (int u = 0; u < 6; u++) {
            int unit = tid + 256 * u;
            int q = unit & 7, n = unit >> 3;
            wreg[u] = *reinterpret_cast<const uint4*>(
                &g_wi[n * 1024 + 2 * kp0 + 4 * q]);
        }
    };

    auto sts_chunk = [&](int buf) {
        uint32_t* sX = smu + PJ_X(buf);
        uint32_t* sW = smu + PJ_W(buf);
        #pragma unroll
        for (int u = 0; u < 2; u++) {
            int r = xr + 32 * u;
            uint4 o;
            split2(xreg[u].x, xreg[u].y, o.x, o.y);
            split2(xreg[u].z, xreg[u].w, o.z, o.w);
            *reinterpret_cast<uint4*>(&sX[r * SXI + 4 * xc]) = o;
        }
        #pragma unroll
        for (int u = 0; u < 6; u++) {
            int unit = tid + 256 * u;
            int q = unit & 7, n = unit >> 3;
            *reinterpret_cast<uint4*>(&sW[n * SWI + 4 * q]) = wreg[u];
        }
    };

    ldg_chunk(0);
    sts_chunk(0);
    __syncthreads();

    const int NCH = En / 32;
    for (int c = 0; c < NCH; c++) {
        const int buf = c & 1;
        if (c + 1 < NCH) ldg_chunk(c + 1);

        const uint32_t* sX = smu + PJ_X(buf);
        const uint32_t* sW = smu + PJ_W(buf);

        #pragma unroll
        for (int kk = 0; kk < 2; kk++) {
            uint32_t ah[4], al[4];
            const int a0 = (16 * wm + g) * SXI + 2 * (8 * kk + tg);
            uint2 u01 = *reinterpret_cast<const uint2*>(&sX[a0]);
            uint2 u23 = *reinterpret_cast<const uint2*>(&sX[a0 + 8]);
            uint2 u45 = *reinterpret_cast<const uint2*>(&sX[a0 + 8 * SXI]);
            uint2 u67 = *reinterpret_cast<const uint2*>(&sX[a0 + 8 * SXI + 8]);
            ah[0] = u01.x; al[0] = u01.y;
            ah[2] = u23.x; al[2] = u23.y;
            ah[1] = u45.x; al[1] = u45.y;
            ah[3] = u67.x; al[3] = u67.y;
            #pragma unroll
            for (int t = 0; t < 12; t++) {
                const int n = wn * 96 + 8 * t + g;
                const int b0 = n * SWI + 2 * (8 * kk + tg);
                uint2 bh = *reinterpret_cast<const uint2*>(&sW[b0]);
                uint2 bl = *reinterpret_cast<const uint2*>(&sW[b0 + 8]);
                mma3(acc[t], ah, al, bh.x, bh.y, bl.x, bl.y);
            }
        }

        if (c + 1 < NCH) sts_chunk(buf ^ 1);
        __syncthreads();
    }

    const int r0 = row0 + 16 * wm + g;
    #pragma unroll
    for (int t = 0; t < 12; t++) {
        const int col = wn * 96 + 8 * t + 2 * tg;
        float a0 = acc[t][0] + sB[col];
        float a1 = acc[t][1] + sB[col + 1];
        float a2 = acc[t][2] + sB[col];
        float a3 = acc[t][3] + sB[col + 1];
        if (col < 64) {
            uint2 o;
            split2(a0 * 0.125f, a1 * 0.125f, o.x, o.y);
            *reinterpret_cast<uint2*>(&g_qi[(size_t)r0 * 64 + col]) = o;
            split2(a2 * 0.125f, a3 * 0.125f, o.x, o.y);
            *reinterpret_cast<uint2*>(&g_qi[(size_t)(r0 + 8) * 64 + col]) = o;
        } else if (col < 128) {
            uint2 o;
            split2(a0, a1, o.x, o.y);
            *reinterpret_cast<uint2*>(&g_ki[(size_t)r0 * 64 + col - 64]) = o;
            split2(a2, a3, o.x, o.y);
            *reinterpret_cast<uint2*>(&g_ki[(size_t)(r0 + 8) * 64 + col - 64]) = o;
        } else {
            const int lcol = col - 128;
            float2 v0, v1;
            v0.x = a0; v0.y = a1;
            v1.x = a2; v1.y = a3;
            *reinterpret_cast<float2*>(&g_v[(size_t)r0 * Hn + lcol]) = v0;
            *reinterpret_cast<float2*>(&g_v[(size_t)(r0 + 8) * Hn + lcol]) = v1;
        }
    }
}

// ---------------------------------------------------------------------------
// Flash attention, 4-way split-KV, 3xBF16, cp.async double-buffered K/V/mask.
// P overlays the CURRENT K buffer (disjoint from the prefetch target).
// ---------------------------------------------------------------------------
#define SKI 72
#define SVI 72
#define BUFK(b) ((b) * 64 * SKI)
#define BUFV(b) (2 * 64 * SKI + (b) * 64 * SVI)
#define BUFM(b) (2 * 64 * SKI + 2 * 64 * SVI + (b) * 64)
#define AT_TOT  (2 * 64 * SKI + 2 * 64 * SVI + 128)

__global__ __launch_bounds__(128) void attn_mma_kernel(
    const int* __restrict__ mask)
{
    extern __shared__ uint32_t smu[];
    const uint32_t sbase = smem_u32(smu);

    const int b    = blockIdx.y;
    const int qt   = (gridDim.x - 1) - blockIdx.x;
    const int z    = blockIdx.z;
    const int qbase = qt * 64;
    const int tid  = threadIdx.x;
    const int warp = tid >> 5;
    const int lane = tid & 31;
    const int g    = lane >> 2;
    const int tg   = lane & 3;
    const int wrow = warp * 16;

    const int nt  = qt + 1;
    const int jt_begin = (nt * z) / NSPLIT;
    const int jt_end   = (nt * (z + 1)) / NSPLIT;

    const uint32_t* qip = g_qi + ((size_t)b * Sn + qbase + wrow) * 64;
    const uint32_t* kip = g_ki + (size_t)b * Sn * 64;
    const uint32_t* vip = g_vi + (size_t)b * 64 * 2048;

    auto prefetch = [&](int jt2, int buf) {
        const int kbase = jt2 * 64;
        #pragma unroll
        for (int u = 0; u < 8; u++) {
            int idx = tid + 128 * u;
            int r = idx >> 4, q4 = idx & 15;
            CP16(sbase + 4 * (BUFK(buf) + r * SKI + 4 * q4),
                 kip + (size_t)(kbase + r) * 64 + 4 * q4);
        }
        #pragma unroll
        for (int u = 0; u < 8; u++) {
            int idx = tid + 128 * u;
            int h = idx >> 4, q4 = idx & 15;
            CP16(sbase + 4 * (BUFV(buf) + h * SVI + 4 * q4),
                 vip + (size_t)h * 2048 + kbase + 4 * q4);
        }
        if (tid < 16) {
            CP16(sbase + 4 * (BUFM(buf) + 4 * tid),
                 mask + b * Sn + kbase + 4 * tid);
        }
        CP_COMMIT();
    };

    // Q fragments (already scaled + split by proj)
    uint32_t qh[4][4], ql[4][4];
    #pragma unroll
    for (int kc = 0; kc < 4; kc++) {
        const int hp = 8 * kc + tg;
        uint2 a0 = *reinterpret_cast<const uint2*>(&qip[(size_t)g * 64 + 2 * hp]);
        uint2 a1 = *reinterpret_cast<const uint2*>(&qip[(size_t)(g + 8) * 64 + 2 * hp]);
        uint2 a2 = *reinterpret_cast<const uint2*>(&qip[(size_t)g * 64 + 2 * hp + 8]);
        uint2 a3 = *reinterpret_cast<const uint2*>(&qip[(size_t)(g + 8) * 64 + 2 * hp + 8]);
        qh[kc][0] = a0.x; ql[kc][0] = a0.y;
        qh[kc][1] = a1.x; ql[kc][1] = a1.y;
        qh[kc][2] = a2.x; ql[kc][2] = a2.y;
        qh[kc][3] = a3.x; ql[kc][3] = a3.y;
    }

    float m0 = -1e30f, m1 = -1e30f, l0 = 0.0f, l1 = 0.0f;
    float o[8][4];
    #pragma unroll
    for (int t = 0; t < 8; t++)
        #pragma unroll
        for (int i = 0; i < 4; i++) o[t][i] = 0.0f;

    if (jt_begin < jt_end)
        prefetch(jt_begin, jt_begin & 1);

    for (int jt = jt_begin; jt < jt_end; jt++) {
        const int buf = jt & 1;
        CP_WAIT0();
        __syncthreads();            // current tile resident; prev buffers free
        if (jt + 1 < jt_end)
            prefetch(jt + 1, buf ^ 1);

        uint32_t* sK = smu + BUFK(buf);
        uint32_t* sV = smu + BUFV(buf);
        const int* sMi = (const int*)(smu + BUFM(buf));

        // S = Q * K^T
        float s[8][4];
        #pragma unroll
        for (int t = 0; t < 8; t++)
            #pragma unroll
            for (int i = 0; i < 4; i++) s[t][i] = 0.0f;

        #pragma unroll
        for (int t = 0; t < 8; t++) {
            const int krow = (8 * t + g) * SKI;
            #pragma unroll
            for (int kc = 0; kc < 4; kc++) {
                uint2 b0 = *reinterpret_cast<const uint2*>(
                    &sK[krow + 2 * (8 * kc + tg)]);
                uint2 b1 = *reinterpret_cast<const uint2*>(
                    &sK[krow + 2 * (8 * kc + tg) + 8]);
                mma3(s[t], qh[kc], ql[kc], b0.x, b0.y, b1.x, b1.y);
            }
        }

        // Mask + online softmax (exp in place over s)
        const bool diag = (jt == qt);
        const int lrow0 = wrow + g;
        float rmax0 = -1e30f, rmax1 = -1e30f;
        #pragma unroll
        for (int t = 0; t < 8; t++) {
            const int c = 8 * t + 2 * tg;
            const float pa0 = sMi[c]     ? 0.0f : -1e30f;
            const float pa1 = sMi[c + 1] ? 0.0f : -1e30f;
            s[t][0] += pa0; s[t][1] += pa1;
            s[t][2] += pa0; s[t][3] += pa1;
            if (diag) {
                if (c > lrow0)         s[t][0] = -1e30f;
                if (c + 1 > lrow0)     s[t][1] = -1e30f;
                if (c > lrow0 + 8)     s[t][2] = -1e30f;
                if (c + 1 > lrow0 + 8) s[t][3] = -1e30f;
            }
            rmax0 = fmaxf(rmax0, fmaxf(s[t][0], s[t][1]));
            rmax1 = fmaxf(rmax1, fmaxf(s[t][2], s[t][3]));
        }
        rmax0 = fmaxf(rmax0, __shfl_xor_sync(0xffffffffu, rmax0, 1));
        rmax0 = fmaxf(rmax0, __shfl_xor_sync(0xffffffffu, rmax0, 2));
        rmax1 = fmaxf(rmax1, __shfl_xor_sync(0xffffffffu, rmax1, 1));
        rmax1 = fmaxf(rmax1, __shfl_xor_sync(0xffffffffu, rmax1, 2));

        const float mn0 = fmaxf(m0, rmax0);
        const float mn1 = fmaxf(m1, rmax1);
        const float al0 = __expf(m0 - mn0);
        const float al1 = __expf(m1 - mn1);

        float ps0 = 0.0f, ps1 = 0.0f;
        #pragma unroll
        for (int t = 0; t < 8; t++) {
            s[t][0] = __expf(s[t][0] - mn0);
            s[t][1] = __expf(s[t][1] - mn0);
            s[t][2] = __expf(s[t][2] - mn1);
            s[t][3] = __expf(s[t][3] - mn1);
            ps0 += s[t][0] + s[t][1];
            ps1 += s[t][2] + s[t][3];
        }
        __syncthreads();   // all warps done reading sK -> overlay P

        #pragma unroll
        for (int t = 0; t < 8; t++) {
            uint2 o2;
            split2(s[t][0], s[t][1], o2.x, o2.y);
            *reinterpret_cast<uint2*>(
                &sK[(wrow + g) * SKI + 2 * (4 * t + tg)]) = o2;
            split2(s[t][2], s[t][3], o2.x, o2.y);
            *reinterpret_cast<uint2*>(
                &sK[(wrow + g + 8) * SKI + 2 * (4 * t + tg)]) = o2;
        }
        ps0 += __shfl_xor_sync(0xffffffffu, ps0, 1);
        ps0 += __shfl_xor_sync(0xffffffffu, ps0, 2);
        ps1 += __shfl_xor_sync(0xffffffffu, ps1, 1);
        ps1 += __shfl_xor_sync(0xffffffffu, ps1, 2);

        l0 = l0 * al0 + ps0;
        l1 = l1 * al1 + ps1;
        m0 = mn0;
        m1 = mn1;
        #pragma unroll
        for (int t = 0; t < 8; t++) {
            o[t][0] *= al0; o[t][1] *= al0;
            o[t][2] *= al1; o[t][3] *= al1;
        }
        __syncwarp();      // own P rows visible (only own warp reads them)

        // O += P * V
        #pragma unroll
        for (int kc = 0; kc < 4; kc++) {
            uint32_t ah[4], al_[4];
            const int pr = (wrow + g) * SKI + 2 * (8 * kc + tg);
            uint2 a0 = *reinterpret_cast<const uint2*>(&sK[pr]);
            uint2 a1 = *reinterpret_cast<const uint2*>(&sK[pr + 8 * SKI]);
            uint2 a2 = *reinterpret_cast<const uint2*>(&sK[pr + 8]);
            uint2 a3 = *reinterpret_cast<const uint2*>(&sK[pr + 8 * SKI + 8]);
            ah[0] = a0.x; al_[0] = a0.y;
            ah[1] = a1.x; al_[1] = a1.y;
            ah[2] = a2.x; al_[2] = a2.y;
            ah[3] = a3.x; al_[3] = a3.y;
            #pragma unroll
            for (int t = 0; t < 8; t++) {
                const int vr = (8 * t + g) * SVI + 2 * (8 * kc + tg);
                uint2 b0 = *reinterpret_cast<const uint2*>(&sV[vr]);
                uint2 b1 = *reinterpret_cast<const uint2*>(&sV[vr + 8]);
                mma3(o[t], ah, al_, b0.x, b0.y, b1.x, b1.y);
            }
        }
        // no trailing sync: next iteration's top wait+sync guards buffer reuse
    }

    float* op = g_op + (size_t)z * Bn * Sn * Hn;
    float* ml = g_ml + (size_t)z * Bn * Sn * 2;
    const size_t row0 = (size_t)b * Sn + qbase + wrow + g;
    #pragma unroll
    for (int t = 0; t < 8; t++) {
        const int col = 8 * t + 2 * tg;
        float2 w0, w1;
        w0.x = o[t][0]; w0.y = o[t][1];
        w1.x = o[t][2]; w1.y = o[t][3];
        *reinterpret_cast<float2*>(&op[row0 * Hn + col]) = w0;
        *reinterpret_cast<float2*>(&op[(row0 + 8) * Hn + col]) = w1;
    }
    if (tg == 0) {
        ml[row0 * 2]           = m0;
        ml[row0 * 2 + 1]       = l0;
        ml[(row0 + 8) * 2]     = m1;
        ml[(row0 + 8) * 2 + 1] = l1;
    }
}

// ---------------------------------------------------------------------------
// Merge the 4 KV splits
// ---------------------------------------------------------------------------
__global__ __launch_bounds__(256) void merge_kernel(float* __restrict__ out)
{
    const int tid = threadIdx.x;
    const int row = blockIdx.x * 16 + (tid >> 4);
    const int c4  = (tid & 15) * 4;

    float mz[NSPLIT], lz[NSPLIT];
    float m = -1e30f;
    #pragma unroll
    for (int zz = 0; zz < NSPLIT; zz++) {
        mz[zz] = g_ml[(size_t)zz * Bn * Sn * 2 + row * 2];
        lz[zz] = g_ml[(size_t)zz * Bn * Sn * 2 + row * 2 + 1];
        m = fmaxf(m, mz[zz]);
    }
    float denom = 0.0f;
    float w[NSPLIT];
    #pragma unroll
    for (int zz = 0; zz < NSPLIT; zz++) {
        w[zz] = __expf(mz[zz] - m);
        denom += w[zz] * lz[zz];
    }
    const float inv = 1.0f / denom;

    float4 r;
    r.x = 0.0f; r.y = 0.0f; r.z = 0.0f; r.w = 0.0f;
    #pragma unroll
    for (int zz = 0; zz < NSPLIT; zz++) {
        float4 a = *reinterpret_cast<const float4*>(
            &g_op[(size_t)zz * Bn * Sn * Hn + (size_t)row * Hn + c4]);
        r.x += w[zz] * a.x;
        r.y += w[zz] * a.y;
        r.z += w[zz] * a.z;
        r.w += w[zz] * a.w;
    }
    r.x *= inv; r.y *= inv; r.z *= inv; r.w *= inv;
    *reinterpret_cast<float4*>(&out[(size_t)row * Hn + c4]) = r;
}

extern "C" void kernel_launch(void* const* d_in, const int* in_sizes, int n_in,
                              void* d_out, int out_size)
{
    const float* x    = (const float*)d_in[0];
    const int*   mask = (const int*)d_in[1];
    const float* Wq   = (const float*)d_in[2];
    const float* bq   = (const float*)d_in[3];
    const float* Wk   = (const float*)d_in[4];
    const float* bk   = (const float*)d_in[5];
    const float* Wv   = (const float*)d_in[6];
    const float* bv   = (const float*)d_in[7];
    float* out = (float*)d_out;

    cudaFuncSetAttribute(proj_mma_kernel,
                         cudaFuncAttributeMaxDynamicSharedMemorySize,
                         PJ_TOT * (int)sizeof(uint32_t));
    cudaFuncSetAttribute(attn_mma_kernel,
                         cudaFuncAttributeMaxDynamicSharedMemorySize,
                         AT_TOT * (int)sizeof(uint32_t));

    wsplit_kernel<<<384, 256>>>(Wq, Wk, Wv);

    proj_mma_kernel<<<Bn * Sn / 64, 256, PJ_TOT * sizeof(uint32_t)>>>(
        x, bq, bk, bv);

    dim3 gvs(Sn / 64, Bn);
    vsplit_kernel<<<gvs, 256>>>();

    dim3 gattn(Sn / 64, Bn, NSPLIT);
    attn_mma_kernel<<<gattn, 128, AT_TOT * sizeof(uint32_t)>>>(mask);

    merge_kernel<<<Bn * Sn / 16, 256>>>(out);
}